// round 15
// baseline (speedup 1.0000x reference)
#include <cuda_runtime.h>
#include <cuda_fp16.h>
#include <cstdint>

#define S_LEN 2048
#define NBATCH 4
#define EMB 1024
#define NH 16
#define HD 64
#define MSZ (NBATCH * S_LEN * EMB)

// ---------------------------------------------------------------------------
// Scratch (allocation-free rule: __device__ globals)
// ---------------------------------------------------------------------------
__device__ __half g_wt[4 * EMB * EMB];     // W^T fp16 [4][N][K]
__device__ __half g_x[3][MSZ];             // fp16 casts of inputs; [0] reused for attn out
__device__ __half g_qh[MSZ];               // q (pre-scaled log2e/32) fp16
__device__ __half g_kh[MSZ];               // k fp16
__device__ __half g_vh[MSZ];               // v fp16

// ---------------------------------------------------------------------------
// Base-ISA PTX helpers (harness PTX target is plain sm_103 — no tcgen05)
// ---------------------------------------------------------------------------
__device__ __forceinline__ uint32_t smem_to_u32(const void* p) {
    uint32_t a;
    asm("{ .reg .u64 t; cvta.to.shared.u64 t, %1; cvt.u32.u64 %0, t; }"
        : "=r"(a) : "l"(p));
    return a;
}

__device__ __forceinline__ void ldsm_x4(uint32_t* r, uint32_t addr) {
    asm volatile("ldmatrix.sync.aligned.m8n8.x4.shared.b16 {%0,%1,%2,%3}, [%4];"
                 : "=r"(r[0]), "=r"(r[1]), "=r"(r[2]), "=r"(r[3]) : "r"(addr));
}
__device__ __forceinline__ void ldsm_x4_t(uint32_t* r, uint32_t addr) {
    asm volatile("ldmatrix.sync.aligned.m8n8.x4.trans.shared.b16 {%0,%1,%2,%3}, [%4];"
                 : "=r"(r[0]), "=r"(r[1]), "=r"(r[2]), "=r"(r[3]) : "r"(addr));
}

__device__ __forceinline__ void mma_f16(float* d, const uint32_t* a,
                                        uint32_t b0, uint32_t b1) {
    asm volatile(
        "mma.sync.aligned.m16n8k16.row.col.f32.f16.f16.f32 "
        "{%0,%1,%2,%3}, {%4,%5,%6,%7}, {%8,%9}, {%0,%1,%2,%3};"
        : "+f"(d[0]), "+f"(d[1]), "+f"(d[2]), "+f"(d[3])
        : "r"(a[0]), "r"(a[1]), "r"(a[2]), "r"(a[3]), "r"(b0), "r"(b1));
}

__device__ __forceinline__ void cp16(uint32_t s, const void* g) {
    asm volatile("cp.async.cg.shared.global [%0], [%1], 16;" :: "r"(s), "l"(g));
}
__device__ __forceinline__ void cp_commit() {
    asm volatile("cp.async.commit_group;" ::: "memory");
}
template <int N>
__device__ __forceinline__ void cp_wait() {
    asm volatile("cp.async.wait_group %0;" :: "n"(N) : "memory");
}

__device__ __forceinline__ uint32_t packh2(float a, float b) {
    __half2 h = __floats2half2_rn(a, b);
    return *(uint32_t*)&h;
}
// fp16x2 exp2 (base ISA sm_75+): in/out packed half2
__device__ __forceinline__ uint32_t h2exp2u(uint32_t x) {
    uint32_t r;
    asm("ex2.approx.f16x2 %0, %1;" : "=r"(r) : "r"(x));
    return r;
}

// ---------------------------------------------------------------------------
// Merged weight transpose: 4x W[K][N] fp32 -> Wt[N][K] fp16 (grid.z selects)
// ---------------------------------------------------------------------------
struct TArgs { const float* W[4]; __half* T[4]; };

__global__ void transpose_half4(TArgs args)
{
    __shared__ float t[32][33];
    const int tx = threadIdx.x, ty = threadIdx.y;
    const int bx = blockIdx.x * 32, by = blockIdx.y * 32;
    const float* W = args.W[blockIdx.z];
    __half* T = args.T[blockIdx.z];
#pragma unroll
    for (int j = 0; j < 4; j++)
        t[ty + j * 8][tx] = W[(size_t)(by + ty + j * 8) * EMB + bx + tx];
    __syncthreads();
#pragma unroll
    for (int j = 0; j < 4; j++) {
        float v = t[tx][ty + j * 8];
        T[(size_t)(bx + ty + j * 8) * EMB + by + tx] = __float2half_rn(v);
    }
}

// ---------------------------------------------------------------------------
// Merged cast: 3x fp32 -> fp16 (grid.y selects tensor)
// ---------------------------------------------------------------------------
struct CArgs { const float* src[3]; __half* dst[3]; };

__global__ __launch_bounds__(256)
void cast3h(CArgs args)
{
    const int z = blockIdx.y;
    const int i = blockIdx.x * 256 + threadIdx.x;
    float4 v = ((const float4*)args.src[z])[i];
    __half2 a = __floats2half2_rn(v.x, v.y);
    __half2 b = __floats2half2_rn(v.z, v.w);
    uint2 u = {*(uint32_t*)&a, *(uint32_t*)&b};
    ((uint2*)args.dst[z])[i] = u;
}

// ---------------------------------------------------------------------------
// mma.sync fp16 GEMM (single product): C = A @ W^T + bias
// 128x128 CTA tile, 4 warps x (64x64) warp tiles: 8 ldsm per 32 MMA per k16
// (smem-BW relief). BK=64, 3-stage cp.async ring, 1 sync/kc.
// ---------------------------------------------------------------------------
#define LDTG 72                        // halfs per row (64 + 8 pad)
#define GTBY (128 * LDTG * 2)          // 18432 B per tile
#define GBUF (2 * GTBY)                // A|B per stage = 36864 B
#define GSTG 3
#define GNKC 16                        // EMB / 64

struct GArgs {
    const __half* A[3];
    const __half* B[3];
    const float*  bias[3];
    float         scale[3];
    __half*       Ch[3];
    float*        Cf;
};

template <bool HOUT>
__global__ __launch_bounds__(128, 2)
void gemm_ms(GArgs args)
{
    extern __shared__ char smc[];
    const uint32_t sb = smem_to_u32(smc);
    const int tid = threadIdx.x;
    const int wid = tid >> 5, lane = tid & 31;
    const int m0 = blockIdx.y * 128, n0 = blockIdx.x * 128;
    const int z = blockIdx.z;

    const __half* gp[2] = {args.A[z], args.B[z]};
    const int gbase[2] = {m0, n0};

    const int lrow = (lane & 7) + ((lane >> 3) & 1) * 8;
    const int lcol = (lane >> 4) * 8;
    const uint32_t laneoff = (uint32_t)(lrow * (LDTG * 2) + lcol * 2);

    const int wm = (wid & 1) * 64;
    const int wn = (wid >> 1) * 64;

    float acc[4][8][4];
#pragma unroll
    for (int i = 0; i < 4; i++)
#pragma unroll
        for (int j = 0; j < 8; j++)
#pragma unroll
            for (int e = 0; e < 4; e++) acc[i][j][e] = 0.0f;

    // prologue: stages 0 and 1 (kc 0, 1); 128 threads, 8 chunks/tile/thread
#pragma unroll
    for (int pk = 0; pk < 2; pk++) {
        const uint32_t so = sb + pk * GBUF;
        const int koff = pk * 64;
#pragma unroll
        for (int arr = 0; arr < 2; arr++)
#pragma unroll
            for (int hh = 0; hh < 8; hh++) {
                const int c = tid + hh * 128;      // 1024 chunks per tile
                const int row = c >> 3, c8 = c & 7;
                cp16(so + arr * GTBY + row * (LDTG * 2) + c8 * 16,
                     gp[arr] + (size_t)(gbase[arr] + row) * EMB + koff + c8 * 8);
            }
        cp_commit();
    }

    for (int kc = 0; kc < GNKC; kc++) {
        if (kc == GNKC - 1) cp_wait<0>(); else cp_wait<1>();
        __syncthreads();

        if (kc + 2 < GNKC) {
            const uint32_t so = sb + ((kc + 2) % GSTG) * GBUF;
            const int koff = (kc + 2) * 64;
#pragma unroll
            for (int arr = 0; arr < 2; arr++)
#pragma unroll
                for (int hh = 0; hh < 8; hh++) {
                    const int c = tid + hh * 128;
                    const int row = c >> 3, c8 = c & 7;
                    cp16(so + arr * GTBY + row * (LDTG * 2) + c8 * 16,
                         gp[arr] + (size_t)(gbase[arr] + row) * EMB + koff + c8 * 8);
                }
            cp_commit();
        }

        const uint32_t tb = sb + (kc % GSTG) * GBUF;
#pragma unroll
        for (int ks = 0; ks < 4; ks++) {          // 4 x k16 within BK=64
            uint32_t af[4][4], bf[4][4];
#pragma unroll
            for (int i = 0; i < 4; i++)
                ldsm_x4(af[i], tb + (wm + i * 16) * (LDTG * 2) + ks * 32 + laneoff);
#pragma unroll
            for (int j = 0; j < 4; j++)
                ldsm_x4(bf[j], tb + GTBY + (wn + j * 16) * (LDTG * 2)
                               + ks * 32 + laneoff);
#pragma unroll
            for (int i = 0; i < 4; i++)
#pragma unroll
                for (int j = 0; j < 4; j++) {
                    mma_f16(acc[i][2 * j],     af[i], bf[j][0], bf[j][2]);
                    mma_f16(acc[i][2 * j + 1], af[i], bf[j][1], bf[j][3]);
                }
        }
    }

    const float scale = args.scale[z];
    const float* bias = args.bias[z];
#pragma unroll
    for (int i = 0; i < 4; i++) {
        const int r = m0 + wm + i * 16 + (lane >> 2);
#pragma unroll
        for (int j = 0; j < 8; j++) {
            const int c = n0 + wn + j * 8 + (lane & 3) * 2;
            const float2 bv = *(const float2*)(bias + c);
            float o00 = (acc[i][j][0] + bv.x) * scale;
            float o01 = (acc[i][j][1] + bv.y) * scale;
            float o10 = (acc[i][j][2] + bv.x) * scale;
            float o11 = (acc[i][j][3] + bv.y) * scale;
            if (HOUT) {
                __half* Ch = args.Ch[z];
                *(__half2*)(Ch + (size_t)r * EMB + c) = __floats2half2_rn(o00, o01);
                *(__half2*)(Ch + (size_t)(r + 8) * EMB + c) = __floats2half2_rn(o10, o11);
            } else {
                *(float2*)(args.Cf + (size_t)r * EMB + c) = make_float2(o00, o01);
                *(float2*)(args.Cf + (size_t)(r + 8) * EMB + c) = make_float2(o10, o11);
            }
        }
    }
}

// ---------------------------------------------------------------------------
// Flash attention, fp16 mma.sync. 128 q rows/CTA, 4 warps x m32 warp tile,
// fused per-key-group QK->exp2->PV loop, no-max exp2 softmax, ones-column l.
// 3-stage K/V cp.async ring -> ONE __syncthreads per key tile.
// (unchanged from round 14)
// ---------------------------------------------------------------------------
#define ALD 72
#define AQR 128
#define AKT 64
#define KVB (AKT * ALD * 2)            // 9216
#define ASM_K   (AQR * ALD * 2)        // Q: [0, 18432)
#define ASM_V   (ASM_K + 3 * KVB)      // 46080
#define ASM_MSK (ASM_V + 3 * KVB)      // 73728
#define ASM_TOT (ASM_MSK + 1024)       // 74752

__global__ __launch_bounds__(128, 3)
void attn_mma(const __half* __restrict__ Qh, const __half* __restrict__ Kh,
              const __half* __restrict__ Vh, const int* __restrict__ mask,
              __half* __restrict__ O)
{
    extern __shared__ char sma[];
    const uint32_t sb = smem_to_u32(sma);
    const int* mskp = (const int*)(sma + ASM_MSK);

    const int tid = threadIdx.x, wid = tid >> 5, lane = tid & 31;
    const int qb = blockIdx.x;
    const int n = blockIdx.y >> 4, h = blockIdx.y & 15;
    const int q0 = qb * AQR;

    const size_t qg  = ((size_t)(n * S_LEN + q0)) * EMB + h * HD;
    const size_t kvg = ((size_t)n * S_LEN) * EMB + h * HD;

    const int lrow = (lane & 7) + ((lane >> 3) & 1) * 8;
    const int lcol = (lane >> 4) * 8;
    const uint32_t laneoff = (uint32_t)(lrow * (ALD * 2) + lcol * 2);

    if (tid < 64) {
        uint4 ones = {0x00003C00u, 0u, 0u, 0u};
#pragma unroll
        for (int b = 0; b < 3; b++)
            *(uint4*)(sma + ASM_V + b * KVB + tid * (ALD * 2) + 128) = ones;
    }

#pragma unroll
    for (int i = 0; i < 8; i++) {
        const int c = tid + i * 128;
        const int row = c >> 3, c8 = c & 7;
        cp16(sb + row * (ALD * 2) + c8 * 16, Qh + qg + (size_t)row * EMB + c8 * 8);
    }
#pragma unroll
    for (int pk = 0; pk < 2; pk++) {
        const size_t kvo = kvg + (size_t)pk * AKT * EMB;
        const uint32_t kd = sb + ASM_K + pk * KVB;
        const uint32_t vd = sb + ASM_V + pk * KVB;
#pragma unroll
        for (int i = 0; i < 4; i++) {
            const int c = tid + i * 128;
            const int row = c >> 3, c8 = c & 7;
            cp16(kd + row * (ALD * 2) + c8 * 16, Kh + kvo + (size_t)row * EMB + c8 * 8);
            cp16(vd + row * (ALD * 2) + c8 * 16, Vh + kvo + (size_t)row * EMB + c8 * 8);
        }
        if (tid < 16)
            cp16(sb + ASM_MSK + pk * 256 + tid * 16,
                 mask + n * S_LEN + pk * AKT + tid * 4);
        cp_commit();
    }

    uint32_t qa[2][4][4];
    float o[2][8][4];
#pragma unroll
    for (int mh = 0; mh < 2; mh++)
#pragma unroll
        for (int j = 0; j < 8; j++)
#pragma unroll
            for (int e = 0; e < 4; e++) o[mh][j][e] = 0.0f;
    float ol[2][4] = {{0, 0, 0, 0}, {0, 0, 0, 0}};

    const int NIT = S_LEN / AKT;   // 32
    for (int kt = 0; kt < NIT; kt++) {
        if (kt == NIT - 1) cp_wait<0>(); else cp_wait<1>();
        __syncthreads();

        if (kt + 2 < NIT) {
            const int st = (kt + 2) % 3;
            const size_t kvo = kvg + (size_t)(kt + 2) * AKT * EMB;
            const uint32_t kd = sb + ASM_K + st * KVB;
            const uint32_t vd = sb + ASM_V + st * KVB;
#pragma unroll
            for (int i = 0; i < 4; i++) {
                const int c = tid + i * 128;
                const int row = c >> 3, c8 = c & 7;
                cp16(kd + row * (ALD * 2) + c8 * 16, Kh + kvo + (size_t)row * EMB + c8 * 8);
                cp16(vd + row * (ALD * 2) + c8 * 16, Vh + kvo + (size_t)row * EMB + c8 * 8);
            }
            if (tid < 16)
                cp16(sb + ASM_MSK + st * 256 + tid * 16,
                     mask + n * S_LEN + (kt + 2) * AKT + tid * 4);
            cp_commit();
        }

        if (kt == 0) {
#pragma unroll
            for (int mh = 0; mh < 2; mh++)
#pragma unroll
                for (int t = 0; t < 4; t++)
                    ldsm_x4(qa[mh][t],
                            sb + (wid * 32 + mh * 16) * (ALD * 2) + t * 32 + laneoff);
        }

        const int st = kt % 3;
        const uint32_t kb_ = sb + ASM_K + st * KVB;
        const uint32_t vb_ = sb + ASM_V + st * KVB;
        const int* mk = mskp + st * 64;

#pragma unroll
        for (int g = 0; g < 4; g++) {
            float s2[2][2][4];
#pragma unroll
            for (int mh = 0; mh < 2; mh++)
#pragma unroll
                for (int nh = 0; nh < 2; nh++)
#pragma unroll
                    for (int e = 0; e < 4; e++) s2[mh][nh][e] = 0.0f;
#pragma unroll
            for (int t = 0; t < 4; t++) {
                uint32_t kb[4];
                ldsm_x4(kb, kb_ + (g * 16) * (ALD * 2) + t * 32 + laneoff);
                mma_f16(s2[0][0], qa[0][t], kb[0], kb[2]);
                mma_f16(s2[0][1], qa[0][t], kb[1], kb[3]);
                mma_f16(s2[1][0], qa[1][t], kb[0], kb[2]);
                mma_f16(s2[1][1], qa[1][t], kb[1], kb[3]);
            }
            const int c = g * 16 + (lane & 3) * 2;
            const int2 mv0 = *(const int2*)(mk + c);
            const int2 mv1 = *(const int2*)(mk + c + 8);
            uint32_t pg[2][4];
#pragma unroll
            for (int mh = 0; mh < 2; mh++) {
                if (mv0.x == 0) { s2[mh][0][0] = -1e4f; s2[mh][0][2] = -1e4f; }
                if (mv0.y == 0) { s2[mh][0][1] = -1e4f; s2[mh][0][3] = -1e4f; }
                if (mv1.x == 0) { s2[mh][1][0] = -1e4f; s2[mh][1][2] = -1e4f; }
                if (mv1.y == 0) { s2[mh][1][1] = -1e4f; s2[mh][1][3] = -1e4f; }
                pg[mh][0] = h2exp2u(packh2(s2[mh][0][0], s2[mh][0][1]));
                pg[mh][1] = h2exp2u(packh2(s2[mh][0][2], s2[mh][0][3]));
                pg[mh][2] = h2exp2u(packh2(s2[mh][1][0], s2[mh][1][1]));
                pg[mh][3] = h2exp2u(packh2(s2[mh][1][2], s2[mh][1][3]));
            }

#pragma unroll
            for (int jd = 0; jd < 4; jd++) {
                uint32_t vb[4];
                ldsm_x4_t(vb, vb_ + (g * 16 + lrow) * (ALD * 2)
                              + (jd * 16 + lcol) * 2);
                mma_f16(o[0][2 * jd],     pg[0], vb[0], vb[1]);
                mma_f16(o[0][2 * jd + 1], pg[0], vb[2], vb[3]);
                mma_f16(o[1][2 * jd],     pg[1], vb[0], vb[1]);
                mma_f16(o[1][2 * jd + 1], pg[1], vb[2], vb[3]);
            }
            uint32_t vl[4];
            ldsm_x4_t(vl, vb_ + (g * 16 + lrow) * (ALD * 2) + (64 + lcol) * 2);
            mma_f16(ol[0], pg[0], vl[0], vl[1]);
            mma_f16(ol[1], pg[1], vl[0], vl[1]);
        }
    }

    const int qsrc = lane & ~3;
#pragma unroll
    for (int mh = 0; mh < 2; mh++) {
        const float l0 = __shfl_sync(0xffffffffu, ol[mh][0], qsrc);
        const float l1 = __shfl_sync(0xffffffffu, ol[mh][2], qsrc);
        const float i0 = 1.0f / l0, i1 = 1.0f / l1;
        const int r0 = q0 + wid * 32 + mh * 16 + (lane >> 2);
#pragma unroll
        for (int j = 0; j < 8; j++) {
            const int d = h * HD + j * 8 + (lane & 3) * 2;
            const size_t off0 = (size_t)(n * S_LEN + r0) * EMB + d;
            const size_t off1 = off0 + 8 * EMB;
            *(__half2*)(O + off0) = __floats2half2_rn(o[mh][j][0] * i0,
                                                      o[mh][j][1] * i0);
            *(__half2*)(O + off1) = __floats2half2_rn(o[mh][j][2] * i1,
                                                      o[mh][j][3] * i1);
        }
    }
}

// ---------------------------------------------------------------------------
extern "C" void kernel_launch(void* const* d_in, const int* in_sizes, int n_in,
                              void* d_out, int out_size)
{
    const float* values = (const float*)d_in[0];
    const float* keys   = (const float*)d_in[1];
    const float* query  = (const float*)d_in[2];
    const int*   mask   = (const int*)  d_in[3];
    const float* Wv = (const float*)d_in[4];
    const float* bv = (const float*)d_in[5];
    const float* Wk = (const float*)d_in[6];
    const float* bk = (const float*)d_in[7];
    const float* Wq = (const float*)d_in[8];
    const float* bq = (const float*)d_in[9];
    const float* Wo = (const float*)d_in[10];
    const float* bo = (const float*)d_in[11];
    float* out = (float*)d_out;

    __half *wt, *x, *qh, *kh, *vh;
    cudaGetSymbolAddress((void**)&wt, g_wt);
    cudaGetSymbolAddress((void**)&x,  g_x);
    cudaGetSymbolAddress((void**)&qh, g_qh);
    cudaGetSymbolAddress((void**)&kh, g_kh);
    cudaGetSymbolAddress((void**)&vh, g_vh);

    const int gemm_smem = GSTG * GBUF;   // 110592 B
    cudaFuncSetAttribute(gemm_ms<true>,
                         cudaFuncAttributeMaxDynamicSharedMemorySize, gemm_smem);
    cudaFuncSetAttribute(gemm_ms<false>,
                         cudaFuncAttributeMaxDynamicSharedMemorySize, gemm_smem);
    cudaFuncSetAttribute(attn_mma,
                         cudaFuncAttributeMaxDynamicSharedMemorySize, ASM_TOT);

    const size_t WSZ = (size_t)EMB * EMB;
    const int M = NBATCH * S_LEN;

    TArgs ta;
    ta.W[0] = Wq; ta.W[1] = Wk; ta.W[2] = Wv; ta.W[3] = Wo;
    ta.T[0] = wt + 0 * WSZ; ta.T[1] = wt + 1 * WSZ;
    ta.T[2] = wt + 2 * WSZ; ta.T[3] = wt + 3 * WSZ;
    transpose_half4<<<dim3(32, 32, 4), dim3(32, 8)>>>(ta);

    CArgs ca;
    ca.src[0] = query; ca.src[1] = keys; ca.src[2] = values;
    ca.dst[0] = x + 0 * MSZ; ca.dst[1] = x + 1 * MSZ; ca.dst[2] = x + 2 * MSZ;
    cast3h<<<dim3((MSZ / 4) / 256, 3), 256>>>(ca);

    GArgs qkv;
    qkv.A[0] = x + 0 * MSZ; qkv.A[1] = x + 1 * MSZ; qkv.A[2] = x + 2 * MSZ;
    qkv.B[0] = wt + 0 * WSZ; qkv.B[1] = wt + 1 * WSZ; qkv.B[2] = wt + 2 * WSZ;
    qkv.bias[0] = bq; qkv.bias[1] = bk; qkv.bias[2] = bv;
    qkv.scale[0] = 1.44269504089f / 32.0f;   // log2e / sqrt(E)
    qkv.scale[1] = 1.0f; qkv.scale[2] = 1.0f;
    qkv.Ch[0] = qh; qkv.Ch[1] = kh; qkv.Ch[2] = vh;
    qkv.Cf = nullptr;
    gemm_ms<true><<<dim3(EMB / 128, M / 128, 3), 128, gemm_smem>>>(qkv);

    dim3 agrid(S_LEN / AQR, NBATCH * NH);    // (16, 64)
    attn_mma<<<agrid, 128, ASM_TOT>>>(qh, kh, vh, mask, x + 0 * MSZ);

    GArgs oproj;
    oproj.A[0] = x + 0 * MSZ; oproj.A[1] = nullptr; oproj.A[2] = nullptr;
    oproj.B[0] = wt + 3 * WSZ; oproj.B[1] = nullptr; oproj.B[2] = nullptr;
    oproj.bias[0] = bo; oproj.bias[1] = nullptr; oproj.bias[2] = nullptr;
    oproj.scale[0] = 1.0f; oproj.scale[1] = 1.0f; oproj.scale[2] = 1.0f;
    oproj.Ch[0] = nullptr; oproj.Ch[1] = nullptr; oproj.Ch[2] = nullptr;
    oproj.Cf = out;
    gemm_ms<false><<<dim3(EMB / 128, M / 128, 1), 128, gemm_smem>>>(oproj);
}

// round 16
// speedup vs baseline: 1.0256x; 1.0256x over previous
#include <cuda_runtime.h>
#include <cuda_fp16.h>
#include <cstdint>

#define S_LEN 2048
#define NBATCH 4
#define EMB 1024
#define NH 16
#define HD 64
#define MSZ (NBATCH * S_LEN * EMB)

// ---------------------------------------------------------------------------
// Scratch (allocation-free rule: __device__ globals)
// ---------------------------------------------------------------------------
__device__ __half g_wt[4 * EMB * EMB];     // W^T fp16 [4][N][K]
__device__ __half g_x[3][MSZ];             // fp16 casts of inputs; [0] reused for attn out
__device__ __half g_qh[MSZ];               // q (pre-scaled log2e/32) fp16
__device__ __half g_kh[MSZ];               // k fp16
__device__ __half g_vh[MSZ];               // v fp16

// ---------------------------------------------------------------------------
// Base-ISA PTX helpers (harness PTX target is plain sm_103 — no tcgen05)
// ---------------------------------------------------------------------------
__device__ __forceinline__ uint32_t smem_to_u32(const void* p) {
    uint32_t a;
    asm("{ .reg .u64 t; cvta.to.shared.u64 t, %1; cvt.u32.u64 %0, t; }"
        : "=r"(a) : "l"(p));
    return a;
}

__device__ __forceinline__ void ldsm_x4(uint32_t* r, uint32_t addr) {
    asm volatile("ldmatrix.sync.aligned.m8n8.x4.shared.b16 {%0,%1,%2,%3}, [%4];"
                 : "=r"(r[0]), "=r"(r[1]), "=r"(r[2]), "=r"(r[3]) : "r"(addr));
}
__device__ __forceinline__ void ldsm_x4_t(uint32_t* r, uint32_t addr) {
    asm volatile("ldmatrix.sync.aligned.m8n8.x4.trans.shared.b16 {%0,%1,%2,%3}, [%4];"
                 : "=r"(r[0]), "=r"(r[1]), "=r"(r[2]), "=r"(r[3]) : "r"(addr));
}

__device__ __forceinline__ void mma_f16(float* d, const uint32_t* a,
                                        uint32_t b0, uint32_t b1) {
    asm volatile(
        "mma.sync.aligned.m16n8k16.row.col.f32.f16.f16.f32 "
        "{%0,%1,%2,%3}, {%4,%5,%6,%7}, {%8,%9}, {%0,%1,%2,%3};"
        : "+f"(d[0]), "+f"(d[1]), "+f"(d[2]), "+f"(d[3])
        : "r"(a[0]), "r"(a[1]), "r"(a[2]), "r"(a[3]), "r"(b0), "r"(b1));
}

__device__ __forceinline__ void cp16(uint32_t s, const void* g) {
    asm volatile("cp.async.cg.shared.global [%0], [%1], 16;" :: "r"(s), "l"(g));
}
__device__ __forceinline__ void cp_commit() {
    asm volatile("cp.async.commit_group;" ::: "memory");
}
template <int N>
__device__ __forceinline__ void cp_wait() {
    asm volatile("cp.async.wait_group %0;" :: "n"(N) : "memory");
}

__device__ __forceinline__ uint32_t packh2(float a, float b) {
    __half2 h = __floats2half2_rn(a, b);
    return *(uint32_t*)&h;
}
// fp16x2 exp2 (base ISA sm_75+): in/out packed half2
__device__ __forceinline__ uint32_t h2exp2u(uint32_t x) {
    uint32_t r;
    asm("ex2.approx.f16x2 %0, %1;" : "=r"(r) : "r"(x));
    return r;
}
__device__ __forceinline__ float h2sum(uint32_t x) {
    __half2 h = *(__half2*)&x;
    float2 f = __half22float2(h);
    return f.x + f.y;
}

// ---------------------------------------------------------------------------
// Merged weight transpose: 4x W[K][N] fp32 -> Wt[N][K] fp16 (grid.z selects)
// ---------------------------------------------------------------------------
struct TArgs { const float* W[4]; __half* T[4]; };

__global__ void transpose_half4(TArgs args)
{
    __shared__ float t[32][33];
    const int tx = threadIdx.x, ty = threadIdx.y;
    const int bx = blockIdx.x * 32, by = blockIdx.y * 32;
    const float* W = args.W[blockIdx.z];
    __half* T = args.T[blockIdx.z];
#pragma unroll
    for (int j = 0; j < 4; j++)
        t[ty + j * 8][tx] = W[(size_t)(by + ty + j * 8) * EMB + bx + tx];
    __syncthreads();
#pragma unroll
    for (int j = 0; j < 4; j++) {
        float v = t[tx][ty + j * 8];
        T[(size_t)(bx + ty + j * 8) * EMB + by + tx] = __float2half_rn(v);
    }
}

// ---------------------------------------------------------------------------
// Merged cast: 3x fp32 -> fp16 (grid.y selects tensor)
// ---------------------------------------------------------------------------
struct CArgs { const float* src[3]; __half* dst[3]; };

__global__ __launch_bounds__(256)
void cast3h(CArgs args)
{
    const int z = blockIdx.y;
    const int i = blockIdx.x * 256 + threadIdx.x;
    float4 v = ((const float4*)args.src[z])[i];
    __half2 a = __floats2half2_rn(v.x, v.y);
    __half2 b = __floats2half2_rn(v.z, v.w);
    uint2 u = {*(uint32_t*)&a, *(uint32_t*)&b};
    ((uint2*)args.dst[z])[i] = u;
}

// ---------------------------------------------------------------------------
// mma.sync fp16 GEMM (single product): C = A @ W^T + bias
// 128x128 CTA tile, 8 warps x (64x32), BK=64, 3-stage cp.async ring.
// Prefetch issued AFTER the first k-step so MMAs start immediately post-sync.
// ---------------------------------------------------------------------------
#define LDTG 72                        // halfs per row (64 + 8 pad)
#define GTBY (128 * LDTG * 2)          // 18432 B per tile
#define GBUF (2 * GTBY)                // A|B per stage = 36864 B
#define GSTG 3
#define GNKC 16                        // EMB / 64

struct GArgs {
    const __half* A[3];
    const __half* B[3];
    const float*  bias[3];
    float         scale[3];
    __half*       Ch[3];
    float*        Cf;
};

template <bool HOUT>
__global__ __launch_bounds__(256, 2)
void gemm_ms(GArgs args)
{
    extern __shared__ char smc[];
    const uint32_t sb = smem_to_u32(smc);
    const int tid = threadIdx.x;
    const int wid = tid >> 5, lane = tid & 31;
    const int m0 = blockIdx.y * 128, n0 = blockIdx.x * 128;
    const int z = blockIdx.z;

    const __half* gp[2] = {args.A[z], args.B[z]};
    const int gbase[2] = {m0, n0};

    const int lrow = (lane & 7) + ((lane >> 3) & 1) * 8;
    const int lcol = (lane >> 4) * 8;
    const uint32_t laneoff = (uint32_t)(lrow * (LDTG * 2) + lcol * 2);

    const int wm = (wid & 1) * 64;
    const int wn = (wid >> 1) * 32;

    float acc[4][4][4];
#pragma unroll
    for (int i = 0; i < 4; i++)
#pragma unroll
        for (int j = 0; j < 4; j++)
#pragma unroll
            for (int e = 0; e < 4; e++) acc[i][j][e] = 0.0f;

    // prologue: stages 0 and 1 (kc 0, 1)
#pragma unroll
    for (int pk = 0; pk < 2; pk++) {
        const uint32_t so = sb + pk * GBUF;
        const int koff = pk * 64;
#pragma unroll
        for (int arr = 0; arr < 2; arr++)
#pragma unroll
            for (int hh = 0; hh < 4; hh++) {
                const int c = tid + hh * 256;      // 1024 chunks per tile
                const int row = c >> 3, c8 = c & 7;
                cp16(so + arr * GTBY + row * (LDTG * 2) + c8 * 16,
                     gp[arr] + (size_t)(gbase[arr] + row) * EMB + koff + c8 * 8);
            }
        cp_commit();
    }

    for (int kc = 0; kc < GNKC; kc++) {
        if (kc == GNKC - 1) cp_wait<0>(); else cp_wait<1>();
        __syncthreads();

        const uint32_t tb = sb + (kc % GSTG) * GBUF;
#pragma unroll
        for (int ks = 0; ks < 4; ks++) {          // 4 x k16 within BK=64
            uint32_t af[4][4];
#pragma unroll
            for (int i = 0; i < 4; i++)
                ldsm_x4(af[i], tb + (wm + i * 16) * (LDTG * 2) + ks * 32 + laneoff);
            uint32_t b0[4], b1[4];
            {
                const uint32_t bo = tb + GTBY + wn * (LDTG * 2) + ks * 32 + laneoff;
                ldsm_x4(b0, bo);
                ldsm_x4(b1, bo + 16 * (LDTG * 2));
            }
#pragma unroll
            for (int i = 0; i < 4; i++) {
                mma_f16(acc[i][0], af[i], b0[0], b0[2]);
                mma_f16(acc[i][1], af[i], b0[1], b0[3]);
                mma_f16(acc[i][2], af[i], b1[0], b1[2]);
                mma_f16(acc[i][3], af[i], b1[1], b1[3]);
            }

            // issue prefetch AFTER the first k-step: tensor starts immediately
            if (ks == 0 && kc + 2 < GNKC) {
                const uint32_t so = sb + ((kc + 2) % GSTG) * GBUF;
                const int koff = (kc + 2) * 64;
#pragma unroll
                for (int arr = 0; arr < 2; arr++)
#pragma unroll
                    for (int hh = 0; hh < 4; hh++) {
                        const int c = tid + hh * 256;
                        const int row = c >> 3, c8 = c & 7;
                        cp16(so + arr * GTBY + row * (LDTG * 2) + c8 * 16,
                             gp[arr] + (size_t)(gbase[arr] + row) * EMB + koff + c8 * 8);
                    }
                cp_commit();
            }
        }
    }

    const float scale = args.scale[z];
    const float* bias = args.bias[z];
#pragma unroll
    for (int i = 0; i < 4; i++) {
        const int r = m0 + wm + i * 16 + (lane >> 2);
#pragma unroll
        for (int j = 0; j < 4; j++) {
            const int c = n0 + wn + j * 8 + (lane & 3) * 2;
            const float2 bv = *(const float2*)(bias + c);
            float o00 = (acc[i][j][0] + bv.x) * scale;
            float o01 = (acc[i][j][1] + bv.y) * scale;
            float o10 = (acc[i][j][2] + bv.x) * scale;
            float o11 = (acc[i][j][3] + bv.y) * scale;
            if (HOUT) {
                __half* Ch = args.Ch[z];
                *(__half2*)(Ch + (size_t)r * EMB + c) = __floats2half2_rn(o00, o01);
                *(__half2*)(Ch + (size_t)(r + 8) * EMB + c) = __floats2half2_rn(o10, o11);
            } else {
                *(float2*)(args.Cf + (size_t)r * EMB + c) = make_float2(o00, o01);
                *(float2*)(args.Cf + (size_t)(r + 8) * EMB + c) = make_float2(o10, o11);
            }
        }
    }
}

// ---------------------------------------------------------------------------
// Flash attention, fp16 mma.sync. 128 q rows/CTA, 4 warps x m32 warp tile,
// fused per-key-group QK->exp2->PV loop, no-max exp2 softmax.
// Row sums l accumulated in fp32 from the SAME fp16 P values (ALU slots,
// replaces the ones-column MMA: -8 MMA, -4 ldsm per warp-iter).
// 3-stage K/V cp.async ring, prefetch issued after key-group 0.
// ---------------------------------------------------------------------------
#define ALD 72
#define AQR 128
#define AKT 64
#define KVB (AKT * ALD * 2)            // 9216
#define ASM_K   (AQR * ALD * 2)        // Q: [0, 18432)
#define ASM_V   (ASM_K + 3 * KVB)      // 46080
#define ASM_MSK (ASM_V + 3 * KVB)      // 73728
#define ASM_TOT (ASM_MSK + 1024)       // 74752

__global__ __launch_bounds__(128, 3)
void attn_mma(const __half* __restrict__ Qh, const __half* __restrict__ Kh,
              const __half* __restrict__ Vh, const int* __restrict__ mask,
              __half* __restrict__ O)
{
    extern __shared__ char sma[];
    const uint32_t sb = smem_to_u32(sma);
    const int* mskp = (const int*)(sma + ASM_MSK);

    const int tid = threadIdx.x, wid = tid >> 5, lane = tid & 31;
    const int qb = blockIdx.x;
    const int n = blockIdx.y >> 4, h = blockIdx.y & 15;
    const int q0 = qb * AQR;

    const size_t qg  = ((size_t)(n * S_LEN + q0)) * EMB + h * HD;
    const size_t kvg = ((size_t)n * S_LEN) * EMB + h * HD;

    const int lrow = (lane & 7) + ((lane >> 3) & 1) * 8;
    const int lcol = (lane >> 4) * 8;
    const uint32_t laneoff = (uint32_t)(lrow * (ALD * 2) + lcol * 2);

    // prologue: Q tile + KV stages 0,1 + masks
#pragma unroll
    for (int i = 0; i < 8; i++) {
        const int c = tid + i * 128;
        const int row = c >> 3, c8 = c & 7;
        cp16(sb + row * (ALD * 2) + c8 * 16, Qh + qg + (size_t)row * EMB + c8 * 8);
    }
#pragma unroll
    for (int pk = 0; pk < 2; pk++) {
        const size_t kvo = kvg + (size_t)pk * AKT * EMB;
        const uint32_t kd = sb + ASM_K + pk * KVB;
        const uint32_t vd = sb + ASM_V + pk * KVB;
#pragma unroll
        for (int i = 0; i < 4; i++) {
            const int c = tid + i * 128;
            const int row = c >> 3, c8 = c & 7;
            cp16(kd + row * (ALD * 2) + c8 * 16, Kh + kvo + (size_t)row * EMB + c8 * 8);
            cp16(vd + row * (ALD * 2) + c8 * 16, Vh + kvo + (size_t)row * EMB + c8 * 8);
        }
        if (tid < 16)
            cp16(sb + ASM_MSK + pk * 256 + tid * 16,
                 mask + n * S_LEN + pk * AKT + tid * 4);
        cp_commit();
    }

    uint32_t qa[2][4][4];
    float o[2][8][4];
#pragma unroll
    for (int mh = 0; mh < 2; mh++)
#pragma unroll
        for (int j = 0; j < 8; j++)
#pragma unroll
            for (int e = 0; e < 4; e++) o[mh][j][e] = 0.0f;
    float lr[2][2] = {{0.0f, 0.0f}, {0.0f, 0.0f}};   // [mh][row r0/r1] partial sums

    const int NIT = S_LEN / AKT;   // 32
    for (int kt = 0; kt < NIT; kt++) {
        if (kt == NIT - 1) cp_wait<0>(); else cp_wait<1>();
        __syncthreads();

        if (kt == 0) {
#pragma unroll
            for (int mh = 0; mh < 2; mh++)
#pragma unroll
                for (int t = 0; t < 4; t++)
                    ldsm_x4(qa[mh][t],
                            sb + (wid * 32 + mh * 16) * (ALD * 2) + t * 32 + laneoff);
        }

        const int st = kt % 3;
        const uint32_t kb_ = sb + ASM_K + st * KVB;
        const uint32_t vb_ = sb + ASM_V + st * KVB;
        const int* mk = mskp + st * 64;

        // Fused per key-group g: S MMAs -> mask/exp2 -> PV MMAs
#pragma unroll
        for (int g = 0; g < 4; g++) {
            float s2[2][2][4];
#pragma unroll
            for (int mh = 0; mh < 2; mh++)
#pragma unroll
                for (int nh = 0; nh < 2; nh++)
#pragma unroll
                    for (int e = 0; e < 4; e++) s2[mh][nh][e] = 0.0f;
#pragma unroll
            for (int t = 0; t < 4; t++) {
                uint32_t kb[4];
                ldsm_x4(kb, kb_ + (g * 16) * (ALD * 2) + t * 32 + laneoff);
                mma_f16(s2[0][0], qa[0][t], kb[0], kb[2]);
                mma_f16(s2[0][1], qa[0][t], kb[1], kb[3]);
                mma_f16(s2[1][0], qa[1][t], kb[0], kb[2]);
                mma_f16(s2[1][1], qa[1][t], kb[1], kb[3]);
            }

            // prefetch KV stage kt+2 after first key-group's QK MMAs
            if (g == 0 && kt + 2 < NIT) {
                const int pst = (kt + 2) % 3;
                const size_t kvo = kvg + (size_t)(kt + 2) * AKT * EMB;
                const uint32_t kd = sb + ASM_K + pst * KVB;
                const uint32_t vd = sb + ASM_V + pst * KVB;
#pragma unroll
                for (int i = 0; i < 4; i++) {
                    const int c = tid + i * 128;
                    const int row = c >> 3, c8 = c & 7;
                    cp16(kd + row * (ALD * 2) + c8 * 16,
                         Kh + kvo + (size_t)row * EMB + c8 * 8);
                    cp16(vd + row * (ALD * 2) + c8 * 16,
                         Vh + kvo + (size_t)row * EMB + c8 * 8);
                }
                if (tid < 16)
                    cp16(sb + ASM_MSK + pst * 256 + tid * 16,
                         mask + n * S_LEN + (kt + 2) * AKT + tid * 4);
                cp_commit();
            }

            const int c = g * 16 + (lane & 3) * 2;
            const int2 mv0 = *(const int2*)(mk + c);
            const int2 mv1 = *(const int2*)(mk + c + 8);
            uint32_t pg[2][4];
#pragma unroll
            for (int mh = 0; mh < 2; mh++) {
                if (mv0.x == 0) { s2[mh][0][0] = -1e4f; s2[mh][0][2] = -1e4f; }
                if (mv0.y == 0) { s2[mh][0][1] = -1e4f; s2[mh][0][3] = -1e4f; }
                if (mv1.x == 0) { s2[mh][1][0] = -1e4f; s2[mh][1][2] = -1e4f; }
                if (mv1.y == 0) { s2[mh][1][1] = -1e4f; s2[mh][1][3] = -1e4f; }
                pg[mh][0] = h2exp2u(packh2(s2[mh][0][0], s2[mh][0][1]));
                pg[mh][1] = h2exp2u(packh2(s2[mh][0][2], s2[mh][0][3]));
                pg[mh][2] = h2exp2u(packh2(s2[mh][1][0], s2[mh][1][1]));
                pg[mh][3] = h2exp2u(packh2(s2[mh][1][2], s2[mh][1][3]));
                // fp32 row sums of the SAME fp16 P used in PV (ALU slots)
                lr[mh][0] += h2sum(pg[mh][0]) + h2sum(pg[mh][2]);
                lr[mh][1] += h2sum(pg[mh][1]) + h2sum(pg[mh][3]);
            }

#pragma unroll
            for (int jd = 0; jd < 4; jd++) {
                uint32_t vb[4];
                ldsm_x4_t(vb, vb_ + (g * 16 + lrow) * (ALD * 2)
                              + (jd * 16 + lcol) * 2);
                mma_f16(o[0][2 * jd],     pg[0], vb[0], vb[1]);
                mma_f16(o[0][2 * jd + 1], pg[0], vb[2], vb[3]);
                mma_f16(o[1][2 * jd],     pg[1], vb[0], vb[1]);
                mma_f16(o[1][2 * jd + 1], pg[1], vb[2], vb[3]);
            }
        }
    }

    // epilogue: quad-reduce l (cols split across 4 quad lanes), normalize
#pragma unroll
    for (int mh = 0; mh < 2; mh++)
#pragma unroll
        for (int rr = 0; rr < 2; rr++) {
            lr[mh][rr] += __shfl_xor_sync(0xffffffffu, lr[mh][rr], 1);
            lr[mh][rr] += __shfl_xor_sync(0xffffffffu, lr[mh][rr], 2);
        }

#pragma unroll
    for (int mh = 0; mh < 2; mh++) {
        const float i0 = 1.0f / lr[mh][0], i1 = 1.0f / lr[mh][1];
        const int r0 = q0 + wid * 32 + mh * 16 + (lane >> 2);
#pragma unroll
        for (int j = 0; j < 8; j++) {
            const int d = h * HD + j * 8 + (lane & 3) * 2;
            const size_t off0 = (size_t)(n * S_LEN + r0) * EMB + d;
            const size_t off1 = off0 + 8 * EMB;
            *(__half2*)(O + off0) = __floats2half2_rn(o[mh][j][0] * i0,
                                                      o[mh][j][1] * i0);
            *(__half2*)(O + off1) = __floats2half2_rn(o[mh][j][2] * i1,
                                                      o[mh][j][3] * i1);
        }
    }
}

// ---------------------------------------------------------------------------
extern "C" void kernel_launch(void* const* d_in, const int* in_sizes, int n_in,
                              void* d_out, int out_size)
{
    const float* values = (const float*)d_in[0];
    const float* keys   = (const float*)d_in[1];
    const float* query  = (const float*)d_in[2];
    const int*   mask   = (const int*)  d_in[3];
    const float* Wv = (const float*)d_in[4];
    const float* bv = (const float*)d_in[5];
    const float* Wk = (const float*)d_in[6];
    const float* bk = (const float*)d_in[7];
    const float* Wq = (const float*)d_in[8];
    const float* bq = (const float*)d_in[9];
    const float* Wo = (const float*)d_in[10];
    const float* bo = (const float*)d_in[11];
    float* out = (float*)d_out;

    __half *wt, *x, *qh, *kh, *vh;
    cudaGetSymbolAddress((void**)&wt, g_wt);
    cudaGetSymbolAddress((void**)&x,  g_x);
    cudaGetSymbolAddress((void**)&qh, g_qh);
    cudaGetSymbolAddress((void**)&kh, g_kh);
    cudaGetSymbolAddress((void**)&vh, g_vh);

    const int gemm_smem = GSTG * GBUF;   // 110592 B
    cudaFuncSetAttribute(gemm_ms<true>,
                         cudaFuncAttributeMaxDynamicSharedMemorySize, gemm_smem);
    cudaFuncSetAttribute(gemm_ms<false>,
                         cudaFuncAttributeMaxDynamicSharedMemorySize, gemm_smem);
    cudaFuncSetAttribute(attn_mma,
                         cudaFuncAttributeMaxDynamicSharedMemorySize, ASM_TOT);

    const size_t WSZ = (size_t)EMB * EMB;
    const int M = NBATCH * S_LEN;

    TArgs ta;
    ta.W[0] = Wq; ta.W[1] = Wk; ta.W[2] = Wv; ta.W[3] = Wo;
    ta.T[0] = wt + 0 * WSZ; ta.T[1] = wt + 1 * WSZ;
    ta.T[2] = wt + 2 * WSZ; ta.T[3] = wt + 3 * WSZ;
    transpose_half4<<<dim3(32, 32, 4), dim3(32, 8)>>>(ta);

    CArgs ca;
    ca.src[0] = query; ca.src[1] = keys; ca.src[2] = values;
    ca.dst[0] = x + 0 * MSZ; ca.dst[1] = x + 1 * MSZ; ca.dst[2] = x + 2 * MSZ;
    cast3h<<<dim3((MSZ / 4) / 256, 3), 256>>>(ca);

    GArgs qkv;
    qkv.A[0] = x + 0 * MSZ; qkv.A[1] = x + 1 * MSZ; qkv.A[2] = x + 2 * MSZ;
    qkv.B[0] = wt + 0 * WSZ; qkv.B[1] = wt + 1 * WSZ; qkv.B[2] = wt + 2 * WSZ;
    qkv.bias[0] = bq; qkv.bias[1] = bk; qkv.bias[2] = bv;
    qkv.scale[0] = 1.44269504089f / 32.0f;   // log2e / sqrt(E)
    qkv.scale[1] = 1.0f; qkv.scale[2] = 1.0f;
    qkv.Ch[0] = qh; qkv.Ch[1] = kh; qkv.Ch[2] = vh;
    qkv.Cf = nullptr;
    gemm_ms<true><<<dim3(EMB / 128, M / 128, 3), 256, gemm_smem>>>(qkv);

    dim3 agrid(S_LEN / AQR, NBATCH * NH);    // (16, 64)
    attn_mma<<<agrid, 128, ASM_TOT>>>(qh, kh, vh, mask, x + 0 * MSZ);

    GArgs oproj;
    oproj.A[0] = x + 0 * MSZ; oproj.A[1] = nullptr; oproj.A[2] = nullptr;
    oproj.B[0] = wt + 3 * WSZ; oproj.B[1] = nullptr; oproj.B[2] = nullptr;
    oproj.bias[0] = bo; oproj.bias[1] = nullptr; oproj.bias[2] = nullptr;
    oproj.scale[0] = 1.0f; oproj.scale[1] = 1.0f; oproj.scale[2] = 1.0f;
    oproj.Ch[0] = nullptr; oproj.Ch[1] = nullptr; oproj.Ch[2] = nullptr;
    oproj.Cf = out;
    gemm_ms<false><<<dim3(EMB / 128, M / 128, 1), 256, gemm_smem>>>(oproj);
}